// round 15
// baseline (speedup 1.0000x reference)
#include <cuda_runtime.h>
#include <cstdint>

#define BBC 128
#define NF  4096
#define MC  8
#define HD  24

typedef unsigned long long u64;

__device__ __forceinline__ u64 pack2(float a, float b) {
    u64 r; asm("mov.b64 %0, {%1, %2};" : "=l"(r) : "f"(a), "f"(b)); return r;
}
__device__ __forceinline__ float2 unpack2(u64 v) {
    float2 r; asm("mov.b64 {%0, %1}, %2;" : "=f"(r.x), "=f"(r.y) : "l"(v)); return r;
}
__device__ __forceinline__ void ffma2(u64& d, u64 a, u64 b) {
    asm("fma.rn.f32x2 %0, %1, %2, %0;" : "+l"(d) : "l"(a), "l"(b));
}

// ---------------- scratch ----------------
__device__ float g_feat[BBC * HD * NF];
__device__ float g_val [BBC * HD * NF];
__device__ float g_csum[BBC * MC * HD];
__device__ float g_vsum[BBC * MC * HD];
__device__ float g_cn  [BBC * MC * HD];
__device__ float g_vc  [BBC * MC * HD];
__device__ float g_s   [BBC * NF];
__device__ int   g_idx [BBC * NF];
__device__ float g_aggD[BBC * MC];
__device__ float g_agg [BBC * MC * HD];

// ---------------- K0: zero pooled-sum accumulators --------------------------
__global__ void k0_zero(){
    int i = blockIdx.x * 512 + threadIdx.x;
    if (i < BBC * MC * HD) { g_csum[i] = 0.f; g_vsum[i] = 0.f; }
}

// ---------------- K1: fused feat+value GEMM (pair-couts FFMA2) + pooling ----
// grid 2048 (b = bx>>9, tile = bx&511, 64 pts), 256 threads.
// smem floats: xs[96*64]@0, wsT[96*200]@6144 (u64 pairs of couts), psum[768]@25344
#define K1_SMEM (26112 * 4)
__global__ void __launch_bounds__(256, 2)
k1_gemm(const float* __restrict__ x,
        const float* __restrict__ fw, const float* __restrict__ vw,
        const float* __restrict__ fb, const float* __restrict__ vb)
{
    extern __shared__ float sm[];
    float* xs   = sm;
    float* wsT  = sm + 6144;
    float* psum = sm + 25344;
    const u64* wsT8 = (const u64*)wsT;

    const int tid = threadIdx.x;
    const int b   = blockIdx.x >> 9;
    const int sp0 = (blockIdx.x & 511) << 6;

    for (int i = tid; i < 768; i += 256) psum[i] = 0.f;

    const float* xb = x + (size_t)b * 96 * 32768 + sp0;
    for (int i = tid; i < 6144; i += 256)
        xs[i] = xb[(size_t)(i >> 6) * 32768 + (i & 63)];
    // weights transposed: wsT[cin*200 + cout]; couts 0..95 = fw, 96..191 = vw
    for (int i = tid; i < 9216; i += 256) {
        int cout = i / 96, cin = i - cout * 96;
        wsT[cin * 200 + cout]      = fw[i];
        wsT[cin * 200 + 96 + cout] = vw[i];
    }
    __syncthreads();

    const int pg = tid & 15, cg = tid >> 4;
    const int p0 = pg << 2;
    const int jbase = cg * 6;           // u64 pair index; couts cg*12 .. cg*12+11

    u64 acc[4][6];
#pragma unroll
    for (int pt = 0; pt < 4; pt++)
#pragma unroll
        for (int q = 0; q < 6; q++) acc[pt][q] = 0ull;

#pragma unroll 4
    for (int k = 0; k < 96; k++) {
        float4 xv = *(const float4*)&xs[k * 64 + p0];
        u64 xx0 = pack2(xv.x, xv.x), xx1 = pack2(xv.y, xv.y);
        u64 xx2 = pack2(xv.z, xv.z), xx3 = pack2(xv.w, xv.w);
        const u64* wr = wsT8 + k * 100 + jbase;
        u64 w0 = wr[0], w1 = wr[1], w2 = wr[2], w3 = wr[3], w4 = wr[4], w5 = wr[5];
        ffma2(acc[0][0], xx0, w0); ffma2(acc[0][1], xx0, w1); ffma2(acc[0][2], xx0, w2);
        ffma2(acc[0][3], xx0, w3); ffma2(acc[0][4], xx0, w4); ffma2(acc[0][5], xx0, w5);
        ffma2(acc[1][0], xx1, w0); ffma2(acc[1][1], xx1, w1); ffma2(acc[1][2], xx1, w2);
        ffma2(acc[1][3], xx1, w3); ffma2(acc[1][4], xx1, w4); ffma2(acc[1][5], xx1, w5);
        ffma2(acc[2][0], xx2, w0); ffma2(acc[2][1], xx2, w1); ffma2(acc[2][2], xx2, w2);
        ffma2(acc[2][3], xx2, w3); ffma2(acc[2][4], xx2, w4); ffma2(acc[2][5], xx2, w5);
        ffma2(acc[3][0], xx3, w0); ffma2(acc[3][1], xx3, w1); ffma2(acc[3][2], xx3, w2);
        ffma2(acc[3][3], xx3, w3); ffma2(acc[3][4], xx3, w4); ffma2(acc[3][5], xx3, w5);
    }

    // epilogue: folded-layout stores + pooled sums
    const int W  = sp0 >> 10;
    const int h0 = (sp0 >> 5) & 31;
    const int h  = h0 + (p0 >> 5);
    const int D0 = p0 & 31;
    const int f  = ((W >> 4) << 2) | ((h >> 4) << 1) | (D0 >> 4);
    const int n0 = ((W & 15) << 8) | ((h & 15) << 4) | (D0 & 15);
    const int d43 = (p0 >> 3) & 3;

#pragma unroll
    for (int q = 0; q < 6; q++) {
        float2 a0 = unpack2(acc[0][q]), a1 = unpack2(acc[1][q]);
        float2 a2 = unpack2(acc[2][q]), a3 = unpack2(acc[3][q]);
#pragma unroll
        for (int b2 = 0; b2 < 2; b2++) {
            int cout = cg * 12 + 2 * q + b2;
            bool isv = cout >= 96;
            int co = isv ? cout - 96 : cout;
            int e = co / 24, c = co - e * 24;
            float bv = isv ? vb[co] : fb[co];
            float4 o;
            o.x = (b2 ? a0.y : a0.x) + bv;
            o.y = (b2 ? a1.y : a1.x) + bv;
            o.z = (b2 ? a2.y : a2.x) + bv;
            o.w = (b2 ? a3.y : a3.x) + bv;
            int bb = (b * 4 + e) * 8 + f;
            *(float4*)&(isv ? g_val : g_feat)[((size_t)(bb * 24 + c) << 12) + n0] = o;
            atomicAdd(&psum[d43 * 192 + cout], o.x + o.y + o.z + o.w);
        }
    }
    __syncthreads();
    for (int i = tid; i < 768; i += 256) {
        int dd = i / 192, cout = i - dd * 192;
        bool isv = cout >= 96;
        int co = isv ? cout - 96 : cout;
        int e = co / 24, c = co - e * 24;
        int m  = (((W >> 3) & 1) << 2) | (((h0 >> 3) & 1) << 1) | (dd & 1);
        int f2 = ((W >> 4) << 2) | (((h0 >> 4) & 1) << 1) | (dd >> 1);
        int bb = (b * 4 + e) * 8 + f2;
        atomicAdd(&(isv ? g_vsum : g_csum)[(bb * 8 + m) * 24 + c], psum[i]);
    }
}

// ---------------- K2b: normalize centers + zero denominators ----------------
__global__ void k2b_norm()
{
    const int bm = blockIdx.x;
    const int t = threadIdx.x;
    float cm = 0.f, vm = 0.f;
    if (t < 24) {
        cm = g_csum[bm * 24 + t] * (1.f / 512.f);
        vm = g_vsum[bm * 24 + t] * (1.f / 512.f);
    }
    float sq = cm * cm;
    for (int o = 16; o; o >>= 1) sq += __shfl_down_sync(0xFFFFFFFFu, sq, o);
    sq = __shfl_sync(0xFFFFFFFFu, sq, 0);
    float nrm = fmaxf(sqrtf(sq), 1e-12f);
    if (t < 24) {
        g_cn[bm * 24 + t] = cm / nrm;
        g_vc[bm * 24 + t] = vm;
    }
    if (t == 0) g_aggD[bm] = 0.f;
}

// ---------------- K3: sim + argmax + denominators (float4 x4 pts) -----------
// grid = 512 (bb*4+chunk), 256 threads, 4 points per thread
__global__ void k3_assign(const float* __restrict__ alpha_p,
                          const float* __restrict__ beta_p)
{
    const int bb = blockIdx.x >> 2, chunk = blockIdx.x & 3;
    const int t = threadIdx.x;
    __shared__ float cn[8][24];
    __shared__ float accD[8];
    if (t < 192) cn[t / 24][t % 24] = g_cn[bb * 192 + t];
    if (t < 8) accD[t] = 0.f;
    const float alpha = *alpha_p, beta = *beta_p;
    __syncthreads();

    const int n = (chunk << 10) + (t << 2);
    const float* fbase = g_feat + (size_t)bb * 24 * NF + n;

    float4 dm[8];
#pragma unroll
    for (int m = 0; m < 8; m++) dm[m] = make_float4(0.f, 0.f, 0.f, 0.f);
    float4 ns = make_float4(0.f, 0.f, 0.f, 0.f);

#pragma unroll
    for (int c = 0; c < 24; c++) {
        float4 v = *(const float4*)(fbase + c * NF);
        ns.x += v.x * v.x; ns.y += v.y * v.y; ns.z += v.z * v.z; ns.w += v.w * v.w;
#pragma unroll
        for (int m = 0; m < 8; m++) {
            float w = cn[m][c];
            dm[m].x += w * v.x; dm[m].y += w * v.y; dm[m].z += w * v.z; dm[m].w += w * v.w;
        }
    }

    float4 outS; int4 outI;
#define K3_LANE(comp, so, io)                                              \
    { float inv = 1.f / fmaxf(sqrtf(ns.comp), 1e-12f);                      \
      float best = -3.4e38f; int bi = 0;                                    \
      _Pragma("unroll")                                                     \
      for (int m = 0; m < 8; m++) {                                         \
          float z = beta + alpha * dm[m].comp * inv;                        \
          if (z > best) { best = z; bi = m; }                               \
      }                                                                     \
      float s = 1.f / (1.f + expf(-best));                                  \
      so = s; io = bi; atomicAdd(&accD[bi], s); }
    K3_LANE(x, outS.x, outI.x)
    K3_LANE(y, outS.y, outI.y)
    K3_LANE(z, outS.z, outI.z)
    K3_LANE(w, outS.w, outI.w)
#undef K3_LANE

    *(float4*)&g_s[bb * NF + n] = outS;
    *(int4*)&g_idx[bb * NF + n] = outI;
    __syncthreads();
    if (t < 8) atomicAdd(&g_aggD[bb * 8 + t], accD[t]);
}

// ---------------- K4: aggregate numerators + finalize (float4) --------------
__global__ void k4_agg()
{
    const int blk = blockIdx.x;
    const int bb = blk / 24, c = blk % 24;
    const float4* vr = (const float4*)(g_val + (size_t)blk * NF);
    const float4* sr = (const float4*)(g_s + bb * NF);
    const int4*   ir = (const int4*)(g_idx + bb * NF);
    const int t = threadIdx.x;

    float acc[8];
#pragma unroll
    for (int m = 0; m < 8; m++) acc[m] = 0.f;
    for (int k = 0; k < 4; k++) {
        int n4 = t + (k << 8);
        float4 s4 = sr[n4], v4 = vr[n4];
        int4 i4 = ir[n4];
        float px = s4.x * v4.x, py = s4.y * v4.y, pz = s4.z * v4.z, pw = s4.w * v4.w;
#pragma unroll
        for (int m = 0; m < 8; m++)
            acc[m] += (i4.x == m ? px : 0.f) + (i4.y == m ? py : 0.f)
                    + (i4.z == m ? pz : 0.f) + (i4.w == m ? pw : 0.f);
    }
#pragma unroll
    for (int m = 0; m < 8; m++)
        for (int o = 16; o; o >>= 1) acc[m] += __shfl_down_sync(0xFFFFFFFFu, acc[m], o);
    __shared__ float red[8][8];
    int w = t >> 5, l = t & 31;
    if (l == 0)
#pragma unroll
        for (int m = 0; m < 8; m++) red[m][w] = acc[m];
    __syncthreads();
    if (t < 8) {
        float s = 0.f;
#pragma unroll
        for (int j = 0; j < 8; j++) s += red[t][j];
        float dnm = g_aggD[bb * 8 + t];
        g_agg[(bb * 8 + t) * 24 + c] = (s + g_vc[(bb * 8 + t) * 24 + c]) / (dnm + 1.f);
    }
}

// ---------------- K5: dispatch gather + pair-couts FFMA2 proj GEMM ----------
// grid 2048 (64-pt tiles), 256 threads.
// smem floats: xs[96*64]@0, wsT[96*104]@6144, ss[256]@16128, osx[256]@16384
#define K5_SMEM (16640 * 4)
__global__ void __launch_bounds__(256, 2)
k5_proj(const float* __restrict__ pw, const float* __restrict__ pb,
        float* __restrict__ out)
{
    extern __shared__ float sm[];
    float* xs  = sm;
    float* wsT = sm + 6144;
    float* ss  = sm + 16128;
    int*   osx = (int*)(sm + 16384);
    const u64* wsT8 = (const u64*)wsT;

    const int tid = threadIdx.x;
    const int b   = blockIdx.x >> 9;
    const int sp0 = (blockIdx.x & 511) << 6;

    {   // stage s / agg-row offset per (head e, point)
        int e = tid >> 6, pt = tid & 63;
        int sp = sp0 + pt;
        int D = sp & 31, H = (sp >> 5) & 31, W = (sp >> 10) & 31;
        int f = ((W >> 4) << 2) | ((H >> 4) << 1) | (D >> 4);
        int n = ((W & 15) << 8) | ((H & 15) << 4) | (D & 15);
        int bb = (b * 4 + e) * 8 + f;
        ss[tid] = g_s[bb * NF + n];
        osx[tid] = (bb * 8 + g_idx[bb * NF + n]) * 24;
    }
    for (int i = tid; i < 9216; i += 256) {
        int cout = i / 96, cin = i - cout * 96;
        wsT[cin * 104 + cout] = pw[i];
    }
    __syncthreads();

    for (int i = tid; i < 6144; i += 256) {
        int ci = i >> 6, pt = i & 63;
        int e = ci / 24, c = ci - e * 24;
        xs[i] = g_agg[osx[(e << 6) + pt] + c] * ss[(e << 6) + pt];
    }
    __syncthreads();

    const int pg = tid & 15, cg = tid >> 4;
    const int p0 = pg << 2;
    const int jbase = cg * 3;           // couts cg*6 .. cg*6+5

    u64 acc[4][3];
#pragma unroll
    for (int pt = 0; pt < 4; pt++)
#pragma unroll
        for (int q = 0; q < 3; q++) acc[pt][q] = 0ull;

#pragma unroll 4
    for (int k = 0; k < 96; k++) {
        float4 xv = *(const float4*)&xs[k * 64 + p0];
        u64 xx0 = pack2(xv.x, xv.x), xx1 = pack2(xv.y, xv.y);
        u64 xx2 = pack2(xv.z, xv.z), xx3 = pack2(xv.w, xv.w);
        const u64* wr = wsT8 + k * 52 + jbase;
        u64 w0 = wr[0], w1 = wr[1], w2 = wr[2];
        ffma2(acc[0][0], xx0, w0); ffma2(acc[0][1], xx0, w1); ffma2(acc[0][2], xx0, w2);
        ffma2(acc[1][0], xx1, w0); ffma2(acc[1][1], xx1, w1); ffma2(acc[1][2], xx1, w2);
        ffma2(acc[2][0], xx2, w0); ffma2(acc[2][1], xx2, w1); ffma2(acc[2][2], xx2, w2);
        ffma2(acc[3][0], xx3, w0); ffma2(acc[3][1], xx3, w1); ffma2(acc[3][2], xx3, w2);
    }

#pragma unroll
    for (int q = 0; q < 3; q++) {
        float2 a0 = unpack2(acc[0][q]), a1 = unpack2(acc[1][q]);
        float2 a2 = unpack2(acc[2][q]), a3 = unpack2(acc[3][q]);
#pragma unroll
        for (int b2 = 0; b2 < 2; b2++) {
            int cout = cg * 6 + 2 * q + b2;
            float bv = pb[cout];
            float4 o;
            o.x = (b2 ? a0.y : a0.x) + bv;
            o.y = (b2 ? a1.y : a1.x) + bv;
            o.z = (b2 ? a2.y : a2.x) + bv;
            o.w = (b2 ? a3.y : a3.x) + bv;
            *(float4*)&out[((size_t)(b * 96 + cout)) * 32768 + sp0 + p0] = o;
        }
    }
}

// ---------------- launch ------------------------------------------------------
extern "C" void kernel_launch(void* const* d_in, const int* in_sizes, int n_in,
                              void* d_out, int out_size)
{
    const float* x  = (const float*)d_in[0];
    const float* fw = (const float*)d_in[1];
    const float* fb = (const float*)d_in[2];
    const float* vw = (const float*)d_in[3];
    const float* vb = (const float*)d_in[4];
    const float* pw = (const float*)d_in[5];
    const float* pb = (const float*)d_in[6];
    const float* sa = (const float*)d_in[7];
    const float* sb = (const float*)d_in[8];
    float* out = (float*)d_out;

    cudaFuncSetAttribute(k1_gemm, cudaFuncAttributeMaxDynamicSharedMemorySize, K1_SMEM);
    cudaFuncSetAttribute(k5_proj, cudaFuncAttributeMaxDynamicSharedMemorySize, K5_SMEM);

    k0_zero<<<96, 512>>>();
    k1_gemm<<<2048, 256, K1_SMEM>>>(x, fw, vw, fb, vb);
    k2b_norm<<<BBC * MC, 32>>>();
    k3_assign<<<512, 256>>>(sa, sb);
    k4_agg<<<BBC * HD, 256>>>();
    k5_proj<<<2048, 256, K5_SMEM>>>(pw, pb, out);
}

// round 16
// speedup vs baseline: 1.0009x; 1.0009x over previous
#include <cuda_runtime.h>
#include <cstdint>

#define BBC 128
#define NF  4096
#define MC  8
#define HD  24

typedef unsigned long long u64;

__device__ __forceinline__ u64 pack2(float a, float b) {
    u64 r; asm("mov.b64 %0, {%1, %2};" : "=l"(r) : "f"(a), "f"(b)); return r;
}
__device__ __forceinline__ float2 unpack2(u64 v) {
    float2 r; asm("mov.b64 {%0, %1}, %2;" : "=f"(r.x), "=f"(r.y) : "l"(v)); return r;
}
__device__ __forceinline__ void ffma2(u64& d, u64 a, u64 b) {
    asm("fma.rn.f32x2 %0, %1, %2, %0;" : "+l"(d) : "l"(a), "l"(b));
}

// ---------------- scratch ----------------
__device__ float g_feat[BBC * HD * NF];
__device__ float g_val [BBC * HD * NF];
__device__ float g_csum[BBC * MC * HD];
__device__ float g_vsum[BBC * MC * HD];
__device__ float g_cn  [BBC * MC * HD];
__device__ float g_vc  [BBC * MC * HD];
__device__ float g_s   [BBC * NF];
__device__ int   g_idx [BBC * NF];
__device__ float g_aggD[BBC * MC];
__device__ float g_agg [BBC * MC * HD];

// ---------------- K0: zero pooled-sum accumulators --------------------------
__global__ void k0_zero(){
    int i = blockIdx.x * 512 + threadIdx.x;
    if (i < BBC * MC * HD) { g_csum[i] = 0.f; g_vsum[i] = 0.f; }
}

// ---------------- K1: fused feat+value GEMM (pair-couts FFMA2) + pooling ----
// grid 2048 (b = bx>>9, tile = bx&511, 64 pts), 256 threads.
// smem floats: xs[96*64]@0, wsT[96*200]@6144 (u64 pairs of couts), psum[768]@25344
#define K1_SMEM (26112 * 4)
__global__ void __launch_bounds__(256, 2)
k1_gemm(const float* __restrict__ x,
        const float* __restrict__ fw, const float* __restrict__ vw,
        const float* __restrict__ fb, const float* __restrict__ vb)
{
    extern __shared__ float sm[];
    float* xs   = sm;
    float* wsT  = sm + 6144;
    float* psum = sm + 25344;
    const u64* wsT8 = (const u64*)wsT;

    const int tid = threadIdx.x;
    const int b   = blockIdx.x >> 9;
    const int sp0 = (blockIdx.x & 511) << 6;

    for (int i = tid; i < 768; i += 256) psum[i] = 0.f;

    const float* xb = x + (size_t)b * 96 * 32768 + sp0;
    for (int i = tid; i < 6144; i += 256)
        xs[i] = xb[(size_t)(i >> 6) * 32768 + (i & 63)];
    // weights transposed: wsT[cin*200 + cout]; couts 0..95 = fw, 96..191 = vw
    for (int i = tid; i < 9216; i += 256) {
        int cout = i / 96, cin = i - cout * 96;
        wsT[cin * 200 + cout]      = fw[i];
        wsT[cin * 200 + 96 + cout] = vw[i];
    }
    __syncthreads();

    const int pg = tid & 15, cg = tid >> 4;
    const int p0 = pg << 2;
    const int jbase = cg * 6;           // u64 pair index; couts cg*12 .. cg*12+11

    u64 acc[4][6];
#pragma unroll
    for (int pt = 0; pt < 4; pt++)
#pragma unroll
        for (int q = 0; q < 6; q++) acc[pt][q] = 0ull;

#pragma unroll 4
    for (int k = 0; k < 96; k++) {
        float4 xv = *(const float4*)&xs[k * 64 + p0];
        u64 xx0 = pack2(xv.x, xv.x), xx1 = pack2(xv.y, xv.y);
        u64 xx2 = pack2(xv.z, xv.z), xx3 = pack2(xv.w, xv.w);
        const u64* wr = wsT8 + k * 100 + jbase;
        u64 w0 = wr[0], w1 = wr[1], w2 = wr[2], w3 = wr[3], w4 = wr[4], w5 = wr[5];
        ffma2(acc[0][0], xx0, w0); ffma2(acc[0][1], xx0, w1); ffma2(acc[0][2], xx0, w2);
        ffma2(acc[0][3], xx0, w3); ffma2(acc[0][4], xx0, w4); ffma2(acc[0][5], xx0, w5);
        ffma2(acc[1][0], xx1, w0); ffma2(acc[1][1], xx1, w1); ffma2(acc[1][2], xx1, w2);
        ffma2(acc[1][3], xx1, w3); ffma2(acc[1][4], xx1, w4); ffma2(acc[1][5], xx1, w5);
        ffma2(acc[2][0], xx2, w0); ffma2(acc[2][1], xx2, w1); ffma2(acc[2][2], xx2, w2);
        ffma2(acc[2][3], xx2, w3); ffma2(acc[2][4], xx2, w4); ffma2(acc[2][5], xx2, w5);
        ffma2(acc[3][0], xx3, w0); ffma2(acc[3][1], xx3, w1); ffma2(acc[3][2], xx3, w2);
        ffma2(acc[3][3], xx3, w3); ffma2(acc[3][4], xx3, w4); ffma2(acc[3][5], xx3, w5);
    }

    // epilogue: folded-layout stores + pooled sums
    const int W  = sp0 >> 10;
    const int h0 = (sp0 >> 5) & 31;
    const int h  = h0 + (p0 >> 5);
    const int D0 = p0 & 31;
    const int f  = ((W >> 4) << 2) | ((h >> 4) << 1) | (D0 >> 4);
    const int n0 = ((W & 15) << 8) | ((h & 15) << 4) | (D0 & 15);
    const int d43 = (p0 >> 3) & 3;

#pragma unroll
    for (int q = 0; q < 6; q++) {
        float2 a0 = unpack2(acc[0][q]), a1 = unpack2(acc[1][q]);
        float2 a2 = unpack2(acc[2][q]), a3 = unpack2(acc[3][q]);
#pragma unroll
        for (int b2 = 0; b2 < 2; b2++) {
            int cout = cg * 12 + 2 * q + b2;
            bool isv = cout >= 96;
            int co = isv ? cout - 96 : cout;
            int e = co / 24, c = co - e * 24;
            float bv = isv ? vb[co] : fb[co];
            float4 o;
            o.x = (b2 ? a0.y : a0.x) + bv;
            o.y = (b2 ? a1.y : a1.x) + bv;
            o.z = (b2 ? a2.y : a2.x) + bv;
            o.w = (b2 ? a3.y : a3.x) + bv;
            int bb = (b * 4 + e) * 8 + f;
            *(float4*)&(isv ? g_val : g_feat)[((size_t)(bb * 24 + c) << 12) + n0] = o;
            atomicAdd(&psum[d43 * 192 + cout], o.x + o.y + o.z + o.w);
        }
    }
    __syncthreads();
    for (int i = tid; i < 768; i += 256) {
        int dd = i / 192, cout = i - dd * 192;
        bool isv = cout >= 96;
        int co = isv ? cout - 96 : cout;
        int e = co / 24, c = co - e * 24;
        int m  = (((W >> 3) & 1) << 2) | (((h0 >> 3) & 1) << 1) | (dd & 1);
        int f2 = ((W >> 4) << 2) | (((h0 >> 4) & 1) << 1) | (dd >> 1);
        int bb = (b * 4 + e) * 8 + f2;
        atomicAdd(&(isv ? g_vsum : g_csum)[(bb * 8 + m) * 24 + c], psum[i]);
    }
}

// ---------------- K2b: normalize centers + zero denominators ----------------
__global__ void k2b_norm()
{
    const int bm = blockIdx.x;
    const int t = threadIdx.x;
    float cm = 0.f, vm = 0.f;
    if (t < 24) {
        cm = g_csum[bm * 24 + t] * (1.f / 512.f);
        vm = g_vsum[bm * 24 + t] * (1.f / 512.f);
    }
    float sq = cm * cm;
    for (int o = 16; o; o >>= 1) sq += __shfl_down_sync(0xFFFFFFFFu, sq, o);
    sq = __shfl_sync(0xFFFFFFFFu, sq, 0);
    float nrm = fmaxf(sqrtf(sq), 1e-12f);
    if (t < 24) {
        g_cn[bm * 24 + t] = cm / nrm;
        g_vc[bm * 24 + t] = vm;
    }
    if (t == 0) g_aggD[bm] = 0.f;
}

// ---------------- K3: sim + argmax + denominators (float4 x4 pts) -----------
// grid = 512 (bb*4+chunk), 256 threads, 4 points per thread
__global__ void k3_assign(const float* __restrict__ alpha_p,
                          const float* __restrict__ beta_p)
{
    const int bb = blockIdx.x >> 2, chunk = blockIdx.x & 3;
    const int t = threadIdx.x;
    __shared__ float cn[8][24];
    __shared__ float accD[8];
    if (t < 192) cn[t / 24][t % 24] = g_cn[bb * 192 + t];
    if (t < 8) accD[t] = 0.f;
    const float alpha = *alpha_p, beta = *beta_p;
    __syncthreads();

    const int n = (chunk << 10) + (t << 2);
    const float* fbase = g_feat + (size_t)bb * 24 * NF + n;

    float4 dm[8];
#pragma unroll
    for (int m = 0; m < 8; m++) dm[m] = make_float4(0.f, 0.f, 0.f, 0.f);
    float4 ns = make_float4(0.f, 0.f, 0.f, 0.f);

#pragma unroll
    for (int c = 0; c < 24; c++) {
        float4 v = *(const float4*)(fbase + c * NF);
        ns.x += v.x * v.x; ns.y += v.y * v.y; ns.z += v.z * v.z; ns.w += v.w * v.w;
#pragma unroll
        for (int m = 0; m < 8; m++) {
            float w = cn[m][c];
            dm[m].x += w * v.x; dm[m].y += w * v.y; dm[m].z += w * v.z; dm[m].w += w * v.w;
        }
    }

    float4 outS; int4 outI;
#define K3_LANE(comp, so, io)                                              \
    { float inv = 1.f / fmaxf(sqrtf(ns.comp), 1e-12f);                      \
      float best = -3.4e38f; int bi = 0;                                    \
      _Pragma("unroll")                                                     \
      for (int m = 0; m < 8; m++) {                                         \
          float z = beta + alpha * dm[m].comp * inv;                        \
          if (z > best) { best = z; bi = m; }                               \
      }                                                                     \
      float s = 1.f / (1.f + expf(-best));                                  \
      so = s; io = bi; atomicAdd(&accD[bi], s); }
    K3_LANE(x, outS.x, outI.x)
    K3_LANE(y, outS.y, outI.y)
    K3_LANE(z, outS.z, outI.z)
    K3_LANE(w, outS.w, outI.w)
#undef K3_LANE

    *(float4*)&g_s[bb * NF + n] = outS;
    *(int4*)&g_idx[bb * NF + n] = outI;
    __syncthreads();
    if (t < 8) atomicAdd(&g_aggD[bb * 8 + t], accD[t]);
}

// ---------------- K4: aggregate numerators + finalize (float4) --------------
__global__ void k4_agg()
{
    const int blk = blockIdx.x;
    const int bb = blk / 24, c = blk % 24;
    const float4* vr = (const float4*)(g_val + (size_t)blk * NF);
    const float4* sr = (const float4*)(g_s + bb * NF);
    const int4*   ir = (const int4*)(g_idx + bb * NF);
    const int t = threadIdx.x;

    float acc[8];
#pragma unroll
    for (int m = 0; m < 8; m++) acc[m] = 0.f;
    for (int k = 0; k < 4; k++) {
        int n4 = t + (k << 8);
        float4 s4 = sr[n4], v4 = vr[n4];
        int4 i4 = ir[n4];
        float px = s4.x * v4.x, py = s4.y * v4.y, pz = s4.z * v4.z, pw = s4.w * v4.w;
#pragma unroll
        for (int m = 0; m < 8; m++)
            acc[m] += (i4.x == m ? px : 0.f) + (i4.y == m ? py : 0.f)
                    + (i4.z == m ? pz : 0.f) + (i4.w == m ? pw : 0.f);
    }
#pragma unroll
    for (int m = 0; m < 8; m++)
        for (int o = 16; o; o >>= 1) acc[m] += __shfl_down_sync(0xFFFFFFFFu, acc[m], o);
    __shared__ float red[8][8];
    int w = t >> 5, l = t & 31;
    if (l == 0)
#pragma unroll
        for (int m = 0; m < 8; m++) red[m][w] = acc[m];
    __syncthreads();
    if (t < 8) {
        float s = 0.f;
#pragma unroll
        for (int j = 0; j < 8; j++) s += red[t][j];
        float dnm = g_aggD[bb * 8 + t];
        g_agg[(bb * 8 + t) * 24 + c] = (s + g_vc[(bb * 8 + t) * 24 + c]) / (dnm + 1.f);
    }
}

// ---------------- K5: dispatch gather + pair-couts FFMA2 proj GEMM ----------
// grid 2048 (64-pt tiles), 256 threads.
// smem floats: xs[96*64]@0, wsT[96*104]@6144, ss[256]@16128, osx[256]@16384
#define K5_SMEM (16640 * 4)
__global__ void __launch_bounds__(256, 2)
k5_proj(const float* __restrict__ pw, const float* __restrict__ pb,
        float* __restrict__ out)
{
    extern __shared__ float sm[];
    float* xs  = sm;
    float* wsT = sm + 6144;
    float* ss  = sm + 16128;
    int*   osx = (int*)(sm + 16384);
    const u64* wsT8 = (const u64*)wsT;

    const int tid = threadIdx.x;
    const int b   = blockIdx.x >> 9;
    const int sp0 = (blockIdx.x & 511) << 6;

    {   // stage s / agg-row offset per (head e, point)
        int e = tid >> 6, pt = tid & 63;
        int sp = sp0 + pt;
        int D = sp & 31, H = (sp >> 5) & 31, W = (sp >> 10) & 31;
        int f = ((W >> 4) << 2) | ((H >> 4) << 1) | (D >> 4);
        int n = ((W & 15) << 8) | ((H & 15) << 4) | (D & 15);
        int bb = (b * 4 + e) * 8 + f;
        ss[tid] = g_s[bb * NF + n];
        osx[tid] = (bb * 8 + g_idx[bb * NF + n]) * 24;
    }
    for (int i = tid; i < 9216; i += 256) {
        int cout = i / 96, cin = i - cout * 96;
        wsT[cin * 104 + cout] = pw[i];
    }
    __syncthreads();

    for (int i = tid; i < 6144; i += 256) {
        int ci = i >> 6, pt = i & 63;
        int e = ci / 24, c = ci - e * 24;
        xs[i] = g_agg[osx[(e << 6) + pt] + c] * ss[(e << 6) + pt];
    }
    __syncthreads();

    const int pg = tid & 15, cg = tid >> 4;
    const int p0 = pg << 2;
    const int jbase = cg * 3;           // couts cg*6 .. cg*6+5

    u64 acc[4][3];
#pragma unroll
    for (int pt = 0; pt < 4; pt++)
#pragma unroll
        for (int q = 0; q < 3; q++) acc[pt][q] = 0ull;

#pragma unroll 4
    for (int k = 0; k < 96; k++) {
        float4 xv = *(const float4*)&xs[k * 64 + p0];
        u64 xx0 = pack2(xv.x, xv.x), xx1 = pack2(xv.y, xv.y);
        u64 xx2 = pack2(xv.z, xv.z), xx3 = pack2(xv.w, xv.w);
        const u64* wr = wsT8 + k * 52 + jbase;
        u64 w0 = wr[0], w1 = wr[1], w2 = wr[2];
        ffma2(acc[0][0], xx0, w0); ffma2(acc[0][1], xx0, w1); ffma2(acc[0][2], xx0, w2);
        ffma2(acc[1][0], xx1, w0); ffma2(acc[1][1], xx1, w1); ffma2(acc[1][2], xx1, w2);
        ffma2(acc[2][0], xx2, w0); ffma2(acc[2][1], xx2, w1); ffma2(acc[2][2], xx2, w2);
        ffma2(acc[3][0], xx3, w0); ffma2(acc[3][1], xx3, w1); ffma2(acc[3][2], xx3, w2);
    }

#pragma unroll
    for (int q = 0; q < 3; q++) {
        float2 a0 = unpack2(acc[0][q]), a1 = unpack2(acc[1][q]);
        float2 a2 = unpack2(acc[2][q]), a3 = unpack2(acc[3][q]);
#pragma unroll
        for (int b2 = 0; b2 < 2; b2++) {
            int cout = cg * 6 + 2 * q + b2;
            float bv = pb[cout];
            float4 o;
            o.x = (b2 ? a0.y : a0.x) + bv;
            o.y = (b2 ? a1.y : a1.x) + bv;
            o.z = (b2 ? a2.y : a2.x) + bv;
            o.w = (b2 ? a3.y : a3.x) + bv;
            *(float4*)&out[((size_t)(b * 96 + cout)) * 32768 + sp0 + p0] = o;
        }
    }
}

// ---------------- launch ------------------------------------------------------
extern "C" void kernel_launch(void* const* d_in, const int* in_sizes, int n_in,
                              void* d_out, int out_size)
{
    const float* x  = (const float*)d_in[0];
    const float* fw = (const float*)d_in[1];
    const float* fb = (const float*)d_in[2];
    const float* vw = (const float*)d_in[3];
    const float* vb = (const float*)d_in[4];
    const float* pw = (const float*)d_in[5];
    const float* pb = (const float*)d_in[6];
    const float* sa = (const float*)d_in[7];
    const float* sb = (const float*)d_in[8];
    float* out = (float*)d_out;

    cudaFuncSetAttribute(k1_gemm, cudaFuncAttributeMaxDynamicSharedMemorySize, K1_SMEM);
    cudaFuncSetAttribute(k5_proj, cudaFuncAttributeMaxDynamicSharedMemorySize, K5_SMEM);

    k0_zero<<<96, 512>>>();
    k1_gemm<<<2048, 256, K1_SMEM>>>(x, fw, vw, fb, vb);
    k2b_norm<<<BBC * MC, 32>>>();
    k3_assign<<<512, 256>>>(sa, sb);
    k4_agg<<<BBC * HD, 256>>>();
    k5_proj<<<2048, 256, K5_SMEM>>>(pw, pb, out);
}